// round 1
// baseline (speedup 1.0000x reference)
#include <cuda_runtime.h>

#define NUM_BINS 20
#define NWARPS 8
#define THREADS (NWARPS * 32)
#define NBLOCKS 740   // 148 SMs * 5 CTAs (smem-limited occupancy)

// Global scratch (allocation-free rule: __device__ globals)
__device__ float g_binsum[NUM_BINS];
__device__ float g_bincount[NUM_BINS];

__global__ void dwmse_zero_kernel() {
    int i = threadIdx.x;
    if (i < NUM_BINS) {
        g_binsum[i] = 0.0f;
        g_bincount[i] = 0.0f;
    }
}

__global__ __launch_bounds__(THREADS) void dwmse_hist_kernel(
    const float4* __restrict__ pred,
    const float4* __restrict__ target,
    int n4)
{
    // Lane-private sub-histograms: [warp][bin][lane] of float2{sum_sqerr, count}.
    // Each lane owns its own column -> plain RMW, no atomics, no bank conflicts.
    __shared__ float2 s_acc[NWARPS * NUM_BINS * 32];

    const int lane = threadIdx.x & 31;
    const int warp = threadIdx.x >> 5;
    float2* my = s_acc + warp * (NUM_BINS * 32) + lane;

    for (int i = threadIdx.x; i < NWARPS * NUM_BINS * 32; i += THREADS)
        s_acc[i] = make_float2(0.0f, 0.0f);
    __syncthreads();

    const int stride = gridDim.x * THREADS;
    for (int i = blockIdx.x * THREADS + threadIdx.x; i < n4; i += stride) {
        float4 p = __ldg(&pred[i]);
        float4 t = __ldg(&target[i]);

        float d0 = p.x - t.x, d1 = p.y - t.y, d2 = p.z - t.z, d3 = p.w - t.w;
        float se0 = d0 * d0, se1 = d1 * d1, se2 = d2 * d2, se3 = d3 * d3;

        int b0 = min(max((int)(t.x * 20.0f), 0), NUM_BINS - 1);
        int b1 = min(max((int)(t.y * 20.0f), 0), NUM_BINS - 1);
        int b2 = min(max((int)(t.z * 20.0f), 0), NUM_BINS - 1);
        int b3 = min(max((int)(t.w * 20.0f), 0), NUM_BINS - 1);

        float2 c;
        c = my[b0 * 32]; c.x += se0; c.y += 1.0f; my[b0 * 32] = c;
        c = my[b1 * 32]; c.x += se1; c.y += 1.0f; my[b1 * 32] = c;
        c = my[b2 * 32]; c.x += se2; c.y += 1.0f; my[b2 * 32] = c;
        c = my[b3 * 32]; c.x += se3; c.y += 1.0f; my[b3 * 32] = c;
    }
    __syncthreads();

    // Block reduction: thread b reduces all 8*32 cells of bin b, then one
    // global atomicAdd per bin per block (740*20*2 atomics total: trivial).
    // Count partials are integer-valued fp32 < 2^24 -> atomic float add exact.
    for (int b = threadIdx.x; b < NUM_BINS; b += THREADS) {
        float s = 0.0f, cnt = 0.0f;
        #pragma unroll 4
        for (int w = 0; w < NWARPS; w++) {
            const float2* cell = s_acc + w * (NUM_BINS * 32) + b * 32;
            for (int l = 0; l < 32; l++) {
                float2 v = cell[l];
                s += v.x;
                cnt += v.y;
            }
        }
        atomicAdd(&g_binsum[b], s);
        atomicAdd(&g_bincount[b], cnt);
    }
}

__global__ void dwmse_finalize_kernel(float* out, int n) {
    // Single thread: 20 bins, double precision for pow().
    double w[NUM_BINS];
    double tot = 0.0;
    for (int b = 0; b < NUM_BINS; b++) {
        double c = (double)g_bincount[b];
        if (c < 1.0) c = 1.0;
        w[b] = pow(c, -0.9);
        tot += w[b];
    }
    double acc = 0.0;
    for (int b = 0; b < NUM_BINS; b++) {
        double wb = (tot > 0.0) ? (w[b] / tot * (double)NUM_BINS) : w[b];
        if (wb < 1.0) wb = 1.0;
        acc += wb * (double)g_binsum[b];
    }
    *out = (float)(acc / (double)n);
}

extern "C" void kernel_launch(void* const* d_in, const int* in_sizes, int n_in,
                              void* d_out, int out_size) {
    const float* pred = (const float*)d_in[0];
    const float* target = (const float*)d_in[1];
    int n = in_sizes[0];
    int n4 = n / 4;  // n = 2^24, divisible by 4

    dwmse_zero_kernel<<<1, 32>>>();
    dwmse_hist_kernel<<<NBLOCKS, THREADS>>>((const float4*)pred,
                                            (const float4*)target, n4);
    dwmse_finalize_kernel<<<1, 1>>>((float*)d_out, n);
}

// round 2
// speedup vs baseline: 2.4819x; 2.4819x over previous
#include <cuda_runtime.h>

#define NUM_BINS 20
#define NWARPS 8
#define THREADS 256
#define NBLOCKS 740   // 148 SMs * 5 CTAs (smem-limited)
#define KBATCH 2

// Per-block partials {sum_sq_err, count} — no zero-init needed, every slot written.
__device__ float2 g_part[NBLOCKS * NUM_BINS];

__global__ __launch_bounds__(THREADS, 5) void dwmse_hist_kernel(
    const float4* __restrict__ pred,
    const float4* __restrict__ target,
    int n4)
{
    // Lane-private sub-histograms: [warp][bin][lane] float2{sum, count}.
    // Each lane owns its column -> plain LDS/FADD/STS RMW, no atomics,
    // conflict-free (lane stride 8B covers all 32 banks per half-warp phase).
    __shared__ float2 s_acc[NWARPS * NUM_BINS * 32];
    __shared__ float2 s_red[NUM_BINS * NWARPS];

    const int lane = threadIdx.x & 31;
    const int warp = threadIdx.x >> 5;
    float2* my = s_acc + warp * (NUM_BINS * 32) + lane;

    for (int i = threadIdx.x; i < NWARPS * NUM_BINS * 32; i += THREADS)
        s_acc[i] = make_float2(0.0f, 0.0f);
    __syncthreads();

    const int stride = gridDim.x * THREADS * KBATCH;
    for (int base = blockIdx.x * THREADS * KBATCH + threadIdx.x;
         base < n4; base += stride) {
        float4 p[KBATCH], t[KBATCH];
        bool valid[KBATCH];
        // Front-batched loads: 2*KBATCH LDG.128 in flight per thread.
        #pragma unroll
        for (int k = 0; k < KBATCH; k++) {
            int idx = base + k * THREADS;
            valid[k] = idx < n4;
            if (valid[k]) {
                p[k] = __ldg(&pred[idx]);
                t[k] = __ldg(&target[idx]);
            }
        }
        #pragma unroll
        for (int k = 0; k < KBATCH; k++) {
            if (!valid[k]) continue;
            float d0 = p[k].x - t[k].x, d1 = p[k].y - t[k].y;
            float d2 = p[k].z - t[k].z, d3 = p[k].w - t[k].w;
            float se0 = d0 * d0, se1 = d1 * d1, se2 = d2 * d2, se3 = d3 * d3;
            // targets are in [0,1): truncation == floor, only upper clamp needed
            int b0 = min((int)(t[k].x * 20.0f), NUM_BINS - 1);
            int b1 = min((int)(t[k].y * 20.0f), NUM_BINS - 1);
            int b2 = min((int)(t[k].z * 20.0f), NUM_BINS - 1);
            int b3 = min((int)(t[k].w * 20.0f), NUM_BINS - 1);
            float2 c;
            c = my[b0 * 32]; c.x += se0; c.y += 1.0f; my[b0 * 32] = c;
            c = my[b1 * 32]; c.x += se1; c.y += 1.0f; my[b1 * 32] = c;
            c = my[b2 * 32]; c.x += se2; c.y += 1.0f; my[b2 * 32] = c;
            c = my[b3 * 32]; c.x += se3; c.y += 1.0f; my[b3 * 32] = c;
        }
    }
    __syncthreads();

    // Stage 1: 160 threads, each reduces one (bin, warp) column of 32 lanes.
    if (threadIdx.x < NUM_BINS * NWARPS) {
        int b = threadIdx.x / NWARPS;
        int w = threadIdx.x % NWARPS;
        const float2* cell = s_acc + w * (NUM_BINS * 32) + b * 32;
        float s = 0.0f, cnt = 0.0f;
        #pragma unroll
        for (int l = 0; l < 32; l++) {
            float2 v = cell[l];
            s += v.x;
            cnt += v.y;
        }
        s_red[b * NWARPS + w] = make_float2(s, cnt);
    }
    __syncthreads();

    // Stage 2: 20 threads, sum 8 warp-partials, write global partial.
    if (threadIdx.x < NUM_BINS) {
        int b = threadIdx.x;
        float s = 0.0f, cnt = 0.0f;
        #pragma unroll
        for (int w = 0; w < NWARPS; w++) {
            float2 v = s_red[b * NWARPS + w];
            s += v.x;
            cnt += v.y;
        }
        g_part[blockIdx.x * NUM_BINS + b] = make_float2(s, cnt);
    }
}

__global__ __launch_bounds__(NUM_BINS * 32) void dwmse_finalize_kernel(float* out, int n) {
    __shared__ float s_sum[NUM_BINS];
    __shared__ float s_cnt[NUM_BINS];
    __shared__ float s_w[NUM_BINS];

    const int warp = threadIdx.x >> 5;
    const int lane = threadIdx.x & 31;

    // Warp b reduces bin b across all 740 block-partials. Counts are
    // integer-valued fp32 < 2^24 throughout -> exact.
    if (warp < NUM_BINS) {
        float s = 0.0f, c = 0.0f;
        for (int bk = lane; bk < NBLOCKS; bk += 32) {
            float2 v = g_part[bk * NUM_BINS + warp];
            s += v.x;
            c += v.y;
        }
        #pragma unroll
        for (int o = 16; o; o >>= 1) {
            s += __shfl_xor_sync(0xFFFFFFFFu, s, o);
            c += __shfl_xor_sync(0xFFFFFFFFu, c, o);
        }
        if (lane == 0) {
            s_sum[warp] = s;
            s_cnt[warp] = c;
        }
    }
    __syncthreads();

    // 20 parallel float pows (MUFU lg2/ex2 path, ~100 cyc) instead of
    // 20 serial double pows (~60us on one thread).
    if (threadIdx.x < NUM_BINS) {
        float c = fmaxf(s_cnt[threadIdx.x], 1.0f);
        s_w[threadIdx.x] = powf(c, -0.9f);
    }
    __syncthreads();

    if (threadIdx.x == 0) {
        float tot = 0.0f;
        #pragma unroll
        for (int b = 0; b < NUM_BINS; b++) tot += s_w[b];
        float acc = 0.0f;
        #pragma unroll
        for (int b = 0; b < NUM_BINS; b++) {
            float wb = (tot > 0.0f) ? (s_w[b] / tot * (float)NUM_BINS) : s_w[b];
            wb = fmaxf(wb, 1.0f);
            acc += wb * s_sum[b];
        }
        *out = acc / (float)n;
    }
}

extern "C" void kernel_launch(void* const* d_in, const int* in_sizes, int n_in,
                              void* d_out, int out_size) {
    const float* pred = (const float*)d_in[0];
    const float* target = (const float*)d_in[1];
    int n = in_sizes[0];
    int n4 = n / 4;  // n = 2^24

    dwmse_hist_kernel<<<NBLOCKS, THREADS>>>((const float4*)pred,
                                            (const float4*)target, n4);
    dwmse_finalize_kernel<<<1, NUM_BINS * 32>>>((float*)d_out, n);
}